// round 1
// baseline (speedup 1.0000x reference)
#include <cuda_runtime.h>
#include <cstdint>

#define D   128
#define C   21
#define CP  132      // padded W-transpose row stride (floats) — conflict-free LDS.128
#define PROW 32      // padded P-table row (floats) = one 128B line
#define MAXN 50000
#define NODES_PER_BLOCK 8

// Scratch (static device globals — no allocation allowed)
__device__ float g_WsT[C * CP];       // Ms^T: [c][k]
__device__ float g_WdT[C * CP];       // Md^T: [c][k]
__device__ float g_bc[C];             // combined bias
__device__ float g_Ps[MAXN * PROW];   // per-node src projection (+bias)
__device__ float g_Pd[MAXN * PROW];   // per-node dst projection
__device__ int   g_is64;              // edge_index dtype flag

// ---------------------------------------------------------------------------
// Detect whether edge_index is int64 or int32.
// int64 (LE, values in [0, 2^31)): every odd 32-bit word is the zero high half.
// int32: 256 random indices in [0,50000) are all zero with prob ~ (1/50000)^256.
// ---------------------------------------------------------------------------
__global__ void detect_kernel(const uint32_t* __restrict__ ew) {
    int lane = threadIdx.x;
    uint32_t v = 0;
#pragma unroll
    for (int i = 0; i < 8; i++)
        v |= ew[1 + 2 * (lane + 32 * i)];   // odd words 1,3,...,511
#pragma unroll
    for (int o = 16; o; o >>= 1)
        v |= __shfl_xor_sync(0xffffffffu, v, o);
    if (lane == 0) g_is64 = (v == 0u) ? 1 : 0;
}

// ---------------------------------------------------------------------------
// Fold weights: Ms = Wsrc @ Wcls, Md = Wdst @ Wcls (stored transposed, padded),
// bc = b_fuse @ Wcls + b_cls.   Total work ~0.7 MFLOP.
// ---------------------------------------------------------------------------
__global__ void combine_kernel(const float* __restrict__ Wsrc,
                               const float* __restrict__ Wdst,
                               const float* __restrict__ Wcls,
                               const float* __restrict__ bfuse,
                               const float* __restrict__ bcls) {
    int t = blockIdx.x * blockDim.x + threadIdx.x;
    const int total = 2 * D * C;
    if (t < total) {
        int m = t / (D * C);
        int r = t % (D * C);
        int k = r / C;
        int c = r % C;
        const float* W = m ? Wdst : Wsrc;
        float acc = 0.f;
#pragma unroll 4
        for (int j = 0; j < D; j++)
            acc = fmaf(W[k * D + j], Wcls[j * C + c], acc);
        (m ? g_WdT : g_WsT)[c * CP + k] = acc;
    } else if (t < total + C) {
        int c = t - total;
        float acc = bcls[c];
        for (int j = 0; j < D; j++)
            acc = fmaf(bfuse[j], Wcls[j * C + c], acc);
        g_bc[c] = acc;
    }
}

// ---------------------------------------------------------------------------
// Per-node projection: Ps[n][c] = emb[n] . Ms[:,c] + bc[c],
//                      Pd[n][c] = emb[n] . Md[:,c]
// Block = 256 threads = 8 nodes x 32 lanes; lanes 0..20 = output class c.
// W tiles cached in smem (stride 132 -> conflict-free float4 reads).
// ---------------------------------------------------------------------------
__global__ void __launch_bounds__(256) nodeproj_kernel(const float* __restrict__ emb, int N) {
    __shared__ float sWs[C * CP];
    __shared__ float sWd[C * CP];
    for (int i = threadIdx.x; i < C * CP; i += blockDim.x) {
        sWs[i] = g_WsT[i];
        sWd[i] = g_WdT[i];
    }
    __syncthreads();

    int nl = threadIdx.x >> 5;
    int c  = threadIdx.x & 31;
    int n  = blockIdx.x * NODES_PER_BLOCK + nl;
    if (n >= N || c >= C) return;

    const float4* e4  = (const float4*)(emb + (size_t)n * D);
    const float4* ws4 = (const float4*)(sWs + c * CP);
    const float4* wd4 = (const float4*)(sWd + c * CP);

    float as = 0.f, ad = 0.f;
#pragma unroll
    for (int k = 0; k < D / 4; k++) {
        float4 ev = __ldg(e4 + k);   // broadcast across the 32 lanes of this node
        float4 ws = ws4[k];
        float4 wd = wd4[k];
        as = fmaf(ev.x, ws.x, as); as = fmaf(ev.y, ws.y, as);
        as = fmaf(ev.z, ws.z, as); as = fmaf(ev.w, ws.w, as);
        ad = fmaf(ev.x, wd.x, ad); ad = fmaf(ev.y, wd.y, ad);
        ad = fmaf(ev.z, wd.z, ad); ad = fmaf(ev.w, wd.w, ad);
    }
    g_Ps[n * PROW + c] = as + g_bc[c];
    g_Pd[n * PROW + c] = ad;
}

// ---------------------------------------------------------------------------
// Edge kernel: one thread per (edge, class) output.
// logits[e][c] = Ps[src[e]][c] + Pd[dst[e]][c]   (bias already folded into Ps)
// P tables (12.8 MB) stay L2-resident; output stores fully coalesced.
// ---------------------------------------------------------------------------
__global__ void __launch_bounds__(256) edge_kernel(const uint32_t* __restrict__ ew,
                                                   float* __restrict__ out,
                                                   uint32_t E) {
    uint32_t t = blockIdx.x * blockDim.x + threadIdx.x;
    uint32_t total = E * (uint32_t)C;
    if (t >= total) return;
    uint32_t e = t / C;            // compiler magic-number division
    uint32_t c = t - e * C;

    uint32_t s, d;
    if (g_is64) {
        s = ew[2u * (size_t)e];
        d = ew[2u * (size_t)E + 2u * (size_t)e];
    } else {
        s = ew[e];
        d = ew[(size_t)E + e];
    }
    out[t] = __ldg(&g_Ps[s * PROW + c]) + __ldg(&g_Pd[d * PROW + c]);
}

// ---------------------------------------------------------------------------
extern "C" void kernel_launch(void* const* d_in, const int* in_sizes, int n_in,
                              void* d_out, int out_size) {
    const float*    emb   = (const float*)d_in[0];
    const uint32_t* ei    = (const uint32_t*)d_in[1];
    const float*    Wsrc  = (const float*)d_in[2];
    const float*    Wdst  = (const float*)d_in[3];
    const float*    bfuse = (const float*)d_in[4];
    const float*    Wcls  = (const float*)d_in[5];
    const float*    bcls  = (const float*)d_in[6];
    float* out = (float*)d_out;

    int N = in_sizes[0] / D;          // 50000
    int E = in_sizes[1] / 2;          // 1600000 (element count same for i32/i64)

    detect_kernel<<<1, 32>>>(ei);

    int tot1 = 2 * D * C + C;
    combine_kernel<<<(tot1 + 255) / 256, 256>>>(Wsrc, Wdst, Wcls, bfuse, bcls);

    nodeproj_kernel<<<(N + NODES_PER_BLOCK - 1) / NODES_PER_BLOCK, 256>>>(emb, N);

    uint32_t tot3 = (uint32_t)E * (uint32_t)C;
    edge_kernel<<<(tot3 + 255) / 256, 256>>>(ei, out, (uint32_t)E);
}

// round 4
// speedup vs baseline: 2.7466x; 2.7466x over previous
#include <cuda_runtime.h>
#include <cstdint>

#define D    128
#define C    21
#define CP   132      // padded W-transpose row stride (floats) — conflict-free LDS.128
#define PROW 32       // padded P-table row (floats) = one 128B line
#define MAXN 50000
#define NPT  4        // nodes per thread in nodeproj (weight-reg reuse)

// Scratch (static device globals — no allocation allowed)
__device__ float g_WsT[C * CP];       // Ms^T: [c][k]
__device__ float g_WdT[C * CP];       // Md^T: [c][k]
__device__ float g_bc[C];             // combined bias
__device__ float g_Ps[MAXN * PROW];   // per-node src projection (+bias)
__device__ float g_Pd[MAXN * PROW];   // per-node dst projection
__device__ int   g_is64;              // edge_index dtype flag

// ---------------------------------------------------------------------------
// Detect whether edge_index is int64 or int32 (deterministic, capture-safe).
// ---------------------------------------------------------------------------
__global__ void detect_kernel(const uint32_t* __restrict__ ew) {
    int lane = threadIdx.x;
    uint32_t v = 0;
#pragma unroll
    for (int i = 0; i < 8; i++)
        v |= ew[1 + 2 * (lane + 32 * i)];   // odd words: int64 high halves
#pragma unroll
    for (int o = 16; o; o >>= 1)
        v |= __shfl_xor_sync(0xffffffffu, v, o);
    if (lane == 0) g_is64 = (v == 0u) ? 1 : 0;
}

// ---------------------------------------------------------------------------
// Fold weights: Ms = Wsrc @ Wcls, Md = Wdst @ Wcls (transposed, padded),
// bc = b_fuse @ Wcls + b_cls.   Wcls cached in smem, W rows read as float4.
// ---------------------------------------------------------------------------
__global__ void __launch_bounds__(256) combine_kernel(const float* __restrict__ Wsrc,
                                                      const float* __restrict__ Wdst,
                                                      const float* __restrict__ Wcls,
                                                      const float* __restrict__ bfuse,
                                                      const float* __restrict__ bcls) {
    __shared__ float sWc[D * C];          // 128*21 = 2688 floats
    for (int i = threadIdx.x; i < D * C; i += blockDim.x)
        sWc[i] = Wcls[i];
    __syncthreads();

    int t = blockIdx.x * blockDim.x + threadIdx.x;
    const int total = 2 * D * C;
    if (t < total) {
        int m = t / (D * C);
        int r = t % (D * C);
        int k = r / C;                    // consecutive 21 threads share k -> W row broadcast
        int c = r % C;
        const float4* W4 = (const float4*)((m ? Wdst : Wsrc) + (size_t)k * D);
        float acc = 0.f;
#pragma unroll 8
        for (int j = 0; j < D / 4; j++) {
            float4 w = __ldg(W4 + j);
            acc = fmaf(w.x, sWc[(4 * j + 0) * C + c], acc);
            acc = fmaf(w.y, sWc[(4 * j + 1) * C + c], acc);
            acc = fmaf(w.z, sWc[(4 * j + 2) * C + c], acc);
            acc = fmaf(w.w, sWc[(4 * j + 3) * C + c], acc);
        }
        (m ? g_WdT : g_WsT)[c * CP + k] = acc;
    } else if (t < total + C) {
        int c = t - total;
        float acc = bcls[c];
        for (int j = 0; j < D; j++)
            acc = fmaf(bfuse[j], sWc[j * C + c], acc);
        g_bc[c] = acc;
    }
}

// ---------------------------------------------------------------------------
// Per-node projection: warp = (NPT nodes) x (lane = class).
// Weight float4s loaded once per k-step, reused across NPT nodes.
// ---------------------------------------------------------------------------
__global__ void __launch_bounds__(256) nodeproj_kernel(const float* __restrict__ emb, int N) {
    __shared__ float sWs[C * CP];
    __shared__ float sWd[C * CP];
    __shared__ float sbc[C];
    for (int i = threadIdx.x; i < C * CP; i += blockDim.x) {
        sWs[i] = g_WsT[i];
        sWd[i] = g_WdT[i];
    }
    if (threadIdx.x < C) sbc[threadIdx.x] = g_bc[threadIdx.x];
    __syncthreads();

    int wid  = threadIdx.x >> 5;
    int lane = threadIdx.x & 31;
    int n0   = (blockIdx.x * 8 + wid) * NPT;
    if (n0 >= N) return;

    int cc = (lane < C) ? lane : (C - 1);           // clamp: keep smem reads in-bounds
    const float4* ws4 = (const float4*)(sWs + cc * CP);
    const float4* wd4 = (const float4*)(sWd + cc * CP);
    const float4* e4  = (const float4*)(emb + (size_t)n0 * D);

    float as[NPT], ad[NPT];
#pragma unroll
    for (int j = 0; j < NPT; j++) { as[j] = 0.f; ad[j] = 0.f; }

    int nv = N - n0; if (nv > NPT) nv = NPT;

    if (nv == NPT) {
#pragma unroll
        for (int k = 0; k < D / 4; k++) {
            float4 ws = ws4[k];
            float4 wd = wd4[k];
#pragma unroll
            for (int j = 0; j < NPT; j++) {
                float4 ev = __ldg(e4 + (size_t)j * (D / 4) + k);   // broadcast per warp
                as[j] = fmaf(ev.x, ws.x, as[j]); as[j] = fmaf(ev.y, ws.y, as[j]);
                as[j] = fmaf(ev.z, ws.z, as[j]); as[j] = fmaf(ev.w, ws.w, as[j]);
                ad[j] = fmaf(ev.x, wd.x, ad[j]); ad[j] = fmaf(ev.y, wd.y, ad[j]);
                ad[j] = fmaf(ev.z, wd.z, ad[j]); ad[j] = fmaf(ev.w, wd.w, ad[j]);
            }
        }
    } else {
        for (int k = 0; k < D / 4; k++) {
            float4 ws = ws4[k];
            float4 wd = wd4[k];
            for (int j = 0; j < nv; j++) {
                float4 ev = __ldg(e4 + (size_t)j * (D / 4) + k);
                as[j] = fmaf(ev.x, ws.x, as[j]); as[j] = fmaf(ev.y, ws.y, as[j]);
                as[j] = fmaf(ev.z, ws.z, as[j]); as[j] = fmaf(ev.w, ws.w, as[j]);
                ad[j] = fmaf(ev.x, wd.x, ad[j]); ad[j] = fmaf(ev.y, wd.y, ad[j]);
                ad[j] = fmaf(ev.z, wd.z, ad[j]); ad[j] = fmaf(ev.w, wd.w, ad[j]);
            }
        }
    }

    if (lane < C) {
        float bc = sbc[lane];
#pragma unroll
        for (int j = 0; j < NPT; j++) {
            if (j < nv) {
                g_Ps[(size_t)(n0 + j) * PROW + lane] = as[j] + bc;
                g_Pd[(size_t)(n0 + j) * PROW + lane] = ad[j];
            }
        }
    }
}

// ---------------------------------------------------------------------------
// Edge kernel: warp-cooperative. Each warp owns 32 edges:
//  - one coalesced index load (32 edges' s and d at once)
//  - per edge: shfl-broadcast (s,d); lanes 0..20 gather one coalesced row
//    from each P table and store 84B directly.
// ---------------------------------------------------------------------------
__global__ void __launch_bounds__(256) edge_kernel(const uint32_t* __restrict__ ew,
                                                   float* __restrict__ out,
                                                   uint32_t E) {
    uint32_t warp = blockIdx.x * (blockDim.x >> 5) + (threadIdx.x >> 5);
    uint32_t lane = threadIdx.x & 31;
    uint32_t e0   = warp * 32u;
    if (e0 >= E) return;

    uint32_t myE = e0 + lane;
    uint32_t sv = 0, dv = 0;
    bool have = (myE < E);
    int is64 = g_is64;
    if (is64) {
        if (have) {
            sv = ew[2u * (size_t)myE];
            dv = ew[2u * (size_t)E + 2u * (size_t)myE];
        }
    } else {
        if (have) {
            sv = ew[myE];
            dv = ew[(size_t)E + myE];
        }
    }

    const float* __restrict__ Ps = g_Ps;
    const float* __restrict__ Pd = g_Pd;
    uint32_t nIt = E - e0; if (nIt > 32u) nIt = 32u;

    if (nIt == 32u) {
#pragma unroll 8
        for (int it = 0; it < 32; ++it) {
            uint32_t s = __shfl_sync(0xffffffffu, sv, it);
            uint32_t d = __shfl_sync(0xffffffffu, dv, it);
            if (lane < C) {
                float v = __ldg(&Ps[(size_t)s * PROW + lane]) +
                          __ldg(&Pd[(size_t)d * PROW + lane]);
                out[(size_t)(e0 + it) * C + lane] = v;
            }
        }
    } else {
        for (uint32_t it = 0; it < nIt; ++it) {
            uint32_t s = __shfl_sync(0xffffffffu, sv, it);
            uint32_t d = __shfl_sync(0xffffffffu, dv, it);
            if (lane < C) {
                float v = __ldg(&Ps[(size_t)s * PROW + lane]) +
                          __ldg(&Pd[(size_t)d * PROW + lane]);
                out[(size_t)(e0 + it) * C + lane] = v;
            }
        }
    }
}

// ---------------------------------------------------------------------------
extern "C" void kernel_launch(void* const* d_in, const int* in_sizes, int n_in,
                              void* d_out, int out_size) {
    const float*    emb   = (const float*)d_in[0];
    const uint32_t* ei    = (const uint32_t*)d_in[1];
    const float*    Wsrc  = (const float*)d_in[2];
    const float*    Wdst  = (const float*)d_in[3];
    const float*    bfuse = (const float*)d_in[4];
    const float*    Wcls  = (const float*)d_in[5];
    const float*    bcls  = (const float*)d_in[6];
    float* out = (float*)d_out;

    int N = in_sizes[0] / D;          // 50000
    int E = in_sizes[1] / 2;          // 1600000 (element count same for i32/i64)

    detect_kernel<<<1, 32>>>(ei);

    int tot1 = 2 * D * C + C;
    combine_kernel<<<(tot1 + 255) / 256, 256>>>(Wsrc, Wdst, Wcls, bfuse, bcls);

    int nodesPerBlock = 8 * NPT;      // 8 warps x NPT nodes
    nodeproj_kernel<<<(N + nodesPerBlock - 1) / nodesPerBlock, 256>>>(emb, N);

    uint32_t chunks = ((uint32_t)E + 31u) / 32u;   // one warp per 32 edges
    uint32_t blocks = (chunks + 7u) / 8u;          // 8 warps per block
    edge_kernel<<<blocks, 256>>>(ei, out, (uint32_t)E);
}

// round 5
// speedup vs baseline: 2.7861x; 1.0144x over previous
#include <cuda_runtime.h>
#include <cstdint>

#define D    128
#define C    21
#define CP   132      // padded W-transpose row stride (floats) — conflict-free LDS.128
#define PROW 32       // padded P-table row (floats) = one 128B line
#define MAXN 50000
#define NPT  4        // nodes per thread in nodeproj

// Scratch (static device globals — no allocation allowed)
__device__ float g_WsT[C * CP];
__device__ float g_WdT[C * CP];
__device__ float g_bc[C];
__device__ float g_Ps[MAXN * PROW];
__device__ float g_Pd[MAXN * PROW];
__device__ int   g_is64;

// ---- packed fp32x2 FMA (sm_103a FFMA2; PTX-only form) ----------------------
__device__ __forceinline__ unsigned long long fma2(unsigned long long a,
                                                   unsigned long long b,
                                                   unsigned long long c) {
    unsigned long long d;
    asm("fma.rn.f32x2 %0, %1, %2, %3;" : "=l"(d) : "l"(a), "l"(b), "l"(c));
    return d;
}
__device__ __forceinline__ float f2sum(unsigned long long v) {
    uint32_t lo, hi;
    asm("mov.b64 {%0, %1}, %2;" : "=r"(lo), "=r"(hi) : "l"(v));
    return __uint_as_float(lo) + __uint_as_float(hi);
}

// ---------------------------------------------------------------------------
// Detect int64 vs int32 edge_index (deterministic, capture-safe).
// ---------------------------------------------------------------------------
__global__ void detect_kernel(const uint32_t* __restrict__ ew) {
    int lane = threadIdx.x;
    uint32_t v = 0;
#pragma unroll
    for (int i = 0; i < 8; i++)
        v |= ew[1 + 2 * (lane + 32 * i)];   // odd words: int64 high halves
#pragma unroll
    for (int o = 16; o; o >>= 1)
        v |= __shfl_xor_sync(0xffffffffu, v, o);
    if (lane == 0) g_is64 = (v == 0u) ? 1 : 0;
}

// ---------------------------------------------------------------------------
// Fold weights: Ms = Wsrc @ Wcls, Md = Wdst @ Wcls (transposed, padded),
// bc = b_fuse @ Wcls + b_cls.
// ---------------------------------------------------------------------------
__global__ void __launch_bounds__(256) combine_kernel(const float* __restrict__ Wsrc,
                                                      const float* __restrict__ Wdst,
                                                      const float* __restrict__ Wcls,
                                                      const float* __restrict__ bfuse,
                                                      const float* __restrict__ bcls) {
    __shared__ float sWc[D * C];
    for (int i = threadIdx.x; i < D * C; i += blockDim.x)
        sWc[i] = Wcls[i];
    __syncthreads();

    int t = blockIdx.x * blockDim.x + threadIdx.x;
    const int total = 2 * D * C;
    if (t < total) {
        int m = t / (D * C);
        int r = t % (D * C);
        int k = r / C;
        int c = r % C;
        const float4* W4 = (const float4*)((m ? Wdst : Wsrc) + (size_t)k * D);
        float acc = 0.f;
#pragma unroll 8
        for (int j = 0; j < D / 4; j++) {
            float4 w = __ldg(W4 + j);
            acc = fmaf(w.x, sWc[(4 * j + 0) * C + c], acc);
            acc = fmaf(w.y, sWc[(4 * j + 1) * C + c], acc);
            acc = fmaf(w.z, sWc[(4 * j + 2) * C + c], acc);
            acc = fmaf(w.w, sWc[(4 * j + 3) * C + c], acc);
        }
        (m ? g_WdT : g_WsT)[c * CP + k] = acc;
    } else if (t < total + C) {
        int c = t - total;
        float acc = bcls[c];
        for (int j = 0; j < D; j++)
            acc = fmaf(bfuse[j], sWc[j * C + c], acc);
        g_bc[c] = acc;
    }
}

// ---------------------------------------------------------------------------
// Per-node projection with packed f32x2 FMAs: halves FMA-pipe ops vs FFMA.
// Warp = NPT nodes x (lane = class). Weight pairs loaded once, reused 4x.
// ---------------------------------------------------------------------------
__global__ void __launch_bounds__(256) nodeproj_kernel(const float* __restrict__ emb, int N) {
    __shared__ __align__(16) float sWs[C * CP];
    __shared__ __align__(16) float sWd[C * CP];
    __shared__ float sbc[C];
    for (int i = threadIdx.x; i < C * CP; i += blockDim.x) {
        sWs[i] = g_WsT[i];
        sWd[i] = g_WdT[i];
    }
    if (threadIdx.x < C) sbc[threadIdx.x] = g_bc[threadIdx.x];
    __syncthreads();

    int wid  = threadIdx.x >> 5;
    int lane = threadIdx.x & 31;
    int n0   = (blockIdx.x * 8 + wid) * NPT;
    if (n0 >= N) return;

    int cc = (lane < C) ? lane : (C - 1);
    const ulonglong2* ws2 = (const ulonglong2*)(sWs + cc * CP);  // cc*528B: 16B-aligned
    const ulonglong2* wd2 = (const ulonglong2*)(sWd + cc * CP);
    const ulonglong2* e2  = (const ulonglong2*)(emb + (size_t)n0 * D);

    unsigned long long as2[NPT], ad2[NPT];
#pragma unroll
    for (int j = 0; j < NPT; j++) { as2[j] = 0ull; ad2[j] = 0ull; }

    int nv = N - n0; if (nv > NPT) nv = NPT;

    if (nv == NPT) {
#pragma unroll
        for (int k = 0; k < D / 4; k++) {
            ulonglong2 ws = ws2[k];
            ulonglong2 wd = wd2[k];
#pragma unroll
            for (int j = 0; j < NPT; j++) {
                ulonglong2 ev = __ldg(e2 + (size_t)j * (D / 4) + k);  // warp broadcast
                as2[j] = fma2(ev.x, ws.x, as2[j]);
                as2[j] = fma2(ev.y, ws.y, as2[j]);
                ad2[j] = fma2(ev.x, wd.x, ad2[j]);
                ad2[j] = fma2(ev.y, wd.y, ad2[j]);
            }
        }
    } else {
        for (int k = 0; k < D / 4; k++) {
            ulonglong2 ws = ws2[k];
            ulonglong2 wd = wd2[k];
            for (int j = 0; j < nv; j++) {
                ulonglong2 ev = __ldg(e2 + (size_t)j * (D / 4) + k);
                as2[j] = fma2(ev.x, ws.x, as2[j]);
                as2[j] = fma2(ev.y, ws.y, as2[j]);
                ad2[j] = fma2(ev.x, wd.x, ad2[j]);
                ad2[j] = fma2(ev.y, wd.y, ad2[j]);
            }
        }
    }

    if (lane < C) {
        float bc = sbc[lane];
#pragma unroll
        for (int j = 0; j < NPT; j++) {
            if (j < nv) {
                g_Ps[(size_t)(n0 + j) * PROW + lane] = f2sum(as2[j]) + bc;
                g_Pd[(size_t)(n0 + j) * PROW + lane] = f2sum(ad2[j]);
            }
        }
    }
}

// ---------------------------------------------------------------------------
// Edge kernel: warp-cooperative with smem store staging.
//  - one coalesced 32-edge index load per warp
//  - per edge: shfl-broadcast (s,d); all 32 lanes gather (lanes 21-31 read
//    row padding in the same 128B line — free, no predicate on loads);
//    lanes 0..20 write the sum into packed smem staging
//  - warp flushes 672 floats (2688B, 128B-aligned) as coalesced STG.128
// ---------------------------------------------------------------------------
__global__ void __launch_bounds__(256) edge_kernel(const uint32_t* __restrict__ ew,
                                                   float* __restrict__ out,
                                                   uint32_t E) {
    __shared__ __align__(16) float sOut[8][32 * C];   // 8 warps x 672 floats
    uint32_t wid  = threadIdx.x >> 5;
    uint32_t lane = threadIdx.x & 31;
    uint32_t warp = blockIdx.x * 8u + wid;
    uint32_t e0   = warp * 32u;
    if (e0 >= E) return;

    uint32_t myE = e0 + lane;
    bool have = (myE < E);
    uint32_t sv = 0, dv = 0;
    if (g_is64) {
        const uint2* ew2 = (const uint2*)ew;
        if (have) {
            sv = ew2[myE].x;
            dv = ew2[(size_t)E + myE].x;
        }
    } else {
        if (have) {
            sv = ew[myE];
            dv = ew[(size_t)E + myE];
        }
    }

    const float* __restrict__ Ps = g_Ps;
    const float* __restrict__ Pd = g_Pd;
    float* so = &sOut[wid][0];
    uint32_t nIt = E - e0; if (nIt > 32u) nIt = 32u;

    if (nIt == 32u) {
#pragma unroll
        for (int it = 0; it < 32; ++it) {
            uint32_t s = __shfl_sync(0xffffffffu, sv, it);
            uint32_t d = __shfl_sync(0xffffffffu, dv, it);
            float v = __ldg(&Ps[(size_t)s * PROW + lane]) +
                      __ldg(&Pd[(size_t)d * PROW + lane]);
            if (lane < C) so[it * C + lane] = v;
        }
        __syncwarp();

        const float4* s4 = (const float4*)so;
        float4* o4 = (float4*)(out + (size_t)e0 * C);   // 2688B-aligned blocks
#pragma unroll
        for (int i = 0; i < 6; ++i) {
            uint32_t idx = (uint32_t)i * 32u + lane;
            if (idx < (32u * C) / 4u)                    // 168 float4s
                o4[idx] = s4[idx];
        }
    } else {
        for (uint32_t it = 0; it < nIt; ++it) {
            uint32_t s = __shfl_sync(0xffffffffu, sv, it);
            uint32_t d = __shfl_sync(0xffffffffu, dv, it);
            if (lane < C) {
                float v = __ldg(&Ps[(size_t)s * PROW + lane]) +
                          __ldg(&Pd[(size_t)d * PROW + lane]);
                out[(size_t)(e0 + it) * C + lane] = v;
            }
        }
    }
}

// ---------------------------------------------------------------------------
extern "C" void kernel_launch(void* const* d_in, const int* in_sizes, int n_in,
                              void* d_out, int out_size) {
    const float*    emb   = (const float*)d_in[0];
    const uint32_t* ei    = (const uint32_t*)d_in[1];
    const float*    Wsrc  = (const float*)d_in[2];
    const float*    Wdst  = (const float*)d_in[3];
    const float*    bfuse = (const float*)d_in[4];
    const float*    Wcls  = (const float*)d_in[5];
    const float*    bcls  = (const float*)d_in[6];
    float* out = (float*)d_out;

    int N = in_sizes[0] / D;          // 50000
    int E = in_sizes[1] / 2;          // 1600000

    detect_kernel<<<1, 32>>>(ei);

    int tot1 = 2 * D * C + C;
    combine_kernel<<<(tot1 + 255) / 256, 256>>>(Wsrc, Wdst, Wcls, bfuse, bcls);

    int nodesPerBlock = 8 * NPT;
    nodeproj_kernel<<<(N + nodesPerBlock - 1) / nodesPerBlock, 256>>>(emb, N);

    uint32_t warps  = ((uint32_t)E + 31u) / 32u;
    uint32_t blocks = (warps + 7u) / 8u;
    edge_kernel<<<blocks, 256>>>(ei, out, (uint32_t)E);
}

// round 6
// speedup vs baseline: 3.1941x; 1.1464x over previous
#include <cuda_runtime.h>
#include <cstdint>

#define D    128
#define C    21
#define CP   132      // padded W-transpose row stride (floats)
#define PROW 32       // padded P-table row (floats) = one 128B line
#define MAXN 50000
#define NPT  8        // nodes per warp in nodeproj

// Scratch (static device globals — no allocation allowed)
__device__ float g_WsT[C * CP];
__device__ float g_WdT[C * CP];
__device__ float g_bc[C];
__device__ float g_Ps[MAXN * PROW];
__device__ float g_Pd[MAXN * PROW];
__device__ int   g_is64;

// ---- packed fp32x2 ops (sm_103a; PTX-only forms) ---------------------------
__device__ __forceinline__ unsigned long long fma2(unsigned long long a,
                                                   unsigned long long b,
                                                   unsigned long long c) {
    unsigned long long d;
    asm("fma.rn.f32x2 %0, %1, %2, %3;" : "=l"(d) : "l"(a), "l"(b), "l"(c));
    return d;
}
__device__ __forceinline__ unsigned long long add2(unsigned long long a,
                                                   unsigned long long b) {
    unsigned long long d;
    asm("add.rn.f32x2 %0, %1, %2;" : "=l"(d) : "l"(a), "l"(b));
    return d;
}
__device__ __forceinline__ void unpack2(unsigned long long v, float& lo, float& hi) {
    uint32_t l, h;
    asm("mov.b64 {%0, %1}, %2;" : "=r"(l), "=r"(h) : "l"(v));
    lo = __uint_as_float(l); hi = __uint_as_float(h);
}
__device__ __forceinline__ float f2sum(unsigned long long v) {
    float lo, hi; unpack2(v, lo, hi); return lo + hi;
}

// ---------------------------------------------------------------------------
// combine_kernel: folds weights AND does dtype detection (last block).
//  Ms = Wsrc @ Wcls, Md = Wdst @ Wcls (transposed, padded), bc folded bias.
// ---------------------------------------------------------------------------
__global__ void __launch_bounds__(256) combine_kernel(const float* __restrict__ Wsrc,
                                                      const float* __restrict__ Wdst,
                                                      const float* __restrict__ Wcls,
                                                      const float* __restrict__ bfuse,
                                                      const float* __restrict__ bcls,
                                                      const uint32_t* __restrict__ ew) {
    // Last block: int64/int32 detection (warp 0 only)
    if (blockIdx.x == gridDim.x - 1) {
        if (threadIdx.x < 32) {
            int lane = threadIdx.x;
            uint32_t v = 0;
#pragma unroll
            for (int i = 0; i < 8; i++)
                v |= ew[1 + 2 * (lane + 32 * i)];   // odd words: int64 high halves
#pragma unroll
            for (int o = 16; o; o >>= 1)
                v |= __shfl_xor_sync(0xffffffffu, v, o);
            if (lane == 0) g_is64 = (v == 0u) ? 1 : 0;
        }
        return;
    }

    __shared__ float sWc[D * C];
    for (int i = threadIdx.x; i < D * C; i += blockDim.x)
        sWc[i] = Wcls[i];
    __syncthreads();

    int t = blockIdx.x * blockDim.x + threadIdx.x;
    const int total = 2 * D * C;
    if (t < total) {
        int m = t / (D * C);
        int r = t % (D * C);
        int k = r / C;
        int c = r % C;
        const float4* W4 = (const float4*)((m ? Wdst : Wsrc) + (size_t)k * D);
        float acc = 0.f;
#pragma unroll 8
        for (int j = 0; j < D / 4; j++) {
            float4 w = __ldg(W4 + j);
            acc = fmaf(w.x, sWc[(4 * j + 0) * C + c], acc);
            acc = fmaf(w.y, sWc[(4 * j + 1) * C + c], acc);
            acc = fmaf(w.z, sWc[(4 * j + 2) * C + c], acc);
            acc = fmaf(w.w, sWc[(4 * j + 3) * C + c], acc);
        }
        (m ? g_WdT : g_WsT)[c * CP + k] = acc;
    } else if (t < total + C) {
        int c = t - total;
        float acc = bcls[c];
        for (int j = 0; j < D; j++)
            acc = fmaf(bfuse[j], sWc[j * C + c], acc);
        g_bc[c] = acc;
    }
}

// ---------------------------------------------------------------------------
// Per-node projection: warp = NPT nodes x (lane = class), f32x2 FMAs.
// Weight 16B chunks loaded once per k-step, reused across NPT nodes.
// ---------------------------------------------------------------------------
__global__ void __launch_bounds__(256) nodeproj_kernel(const float* __restrict__ emb, int N) {
    __shared__ __align__(16) float sWs[C * CP];
    __shared__ __align__(16) float sWd[C * CP];
    __shared__ float sbc[C];
    for (int i = threadIdx.x; i < C * CP; i += blockDim.x) {
        sWs[i] = g_WsT[i];
        sWd[i] = g_WdT[i];
    }
    if (threadIdx.x < C) sbc[threadIdx.x] = g_bc[threadIdx.x];
    __syncthreads();

    int wid  = threadIdx.x >> 5;
    int lane = threadIdx.x & 31;
    int n0   = (blockIdx.x * 8 + wid) * NPT;
    if (n0 >= N) return;

    int cc = (lane < C) ? lane : (C - 1);
    const ulonglong2* ws2 = (const ulonglong2*)(sWs + cc * CP);  // 528B rows: 16B-aligned
    const ulonglong2* wd2 = (const ulonglong2*)(sWd + cc * CP);
    const ulonglong2* e2  = (const ulonglong2*)(emb + (size_t)n0 * D);

    unsigned long long as2[NPT], ad2[NPT];
#pragma unroll
    for (int j = 0; j < NPT; j++) { as2[j] = 0ull; ad2[j] = 0ull; }

    int nv = N - n0; if (nv > NPT) nv = NPT;

    if (nv == NPT) {
#pragma unroll
        for (int k = 0; k < D / 4; k++) {
            ulonglong2 ws = ws2[k];
            ulonglong2 wd = wd2[k];
#pragma unroll
            for (int j = 0; j < NPT; j++) {
                ulonglong2 ev = __ldg(e2 + (size_t)j * (D / 4) + k);  // warp broadcast
                as2[j] = fma2(ev.x, ws.x, as2[j]);
                as2[j] = fma2(ev.y, ws.y, as2[j]);
                ad2[j] = fma2(ev.x, wd.x, ad2[j]);
                ad2[j] = fma2(ev.y, wd.y, ad2[j]);
            }
        }
    } else {
        for (int k = 0; k < D / 4; k++) {
            ulonglong2 ws = ws2[k];
            ulonglong2 wd = wd2[k];
            for (int j = 0; j < nv; j++) {
                ulonglong2 ev = __ldg(e2 + (size_t)j * (D / 4) + k);
                as2[j] = fma2(ev.x, ws.x, as2[j]);
                as2[j] = fma2(ev.y, ws.y, as2[j]);
                ad2[j] = fma2(ev.x, wd.x, ad2[j]);
                ad2[j] = fma2(ev.y, wd.y, ad2[j]);
            }
        }
    }

    if (lane < C) {
        float bc = sbc[lane];
#pragma unroll
        for (int j = 0; j < NPT; j++) {
            if (j < nv) {
                g_Ps[(size_t)(n0 + j) * PROW + lane] = f2sum(as2[j]) + bc;
                g_Pd[(size_t)(n0 + j) * PROW + lane] = f2sum(ad2[j]);
            }
        }
    }
}

// ---------------------------------------------------------------------------
// Edge kernel: half-warp cooperative, 2 edges per iteration.
//  - one coalesced 32-edge index load per warp
//  - per iter: each 16-lane half gathers one full P row per table as LDG.64
//    (1 L1 wavefront per row, half the instructions of 32-lane/edge form)
//  - packed f32x2 add; direct evict-first STG.32 stores (no smem staging —
//    R5 showed staging ADDS L1 work; 84B blocks can't use aligned wide stores)
// ---------------------------------------------------------------------------
__global__ void __launch_bounds__(256) edge_kernel(const uint32_t* __restrict__ ew,
                                                   float* __restrict__ out,
                                                   uint32_t E) {
    uint32_t wid  = threadIdx.x >> 5;
    uint32_t lane = threadIdx.x & 31;
    uint32_t warp = blockIdx.x * 8u + wid;
    uint32_t e0   = warp * 32u;
    if (e0 >= E) return;

    uint32_t myE = e0 + lane;
    bool have = (myE < E);
    uint32_t sv = 0, dv = 0;
    if (g_is64) {
        const uint2* ew2 = (const uint2*)ew;
        if (have) {
            sv = ew2[myE].x;
            dv = ew2[(size_t)E + myE].x;
        }
    } else {
        if (have) {
            sv = ew[myE];
            dv = ew[(size_t)E + myE];
        }
    }

    const unsigned long long* __restrict__ Ps8 = (const unsigned long long*)g_Ps; // row=16 ull
    const unsigned long long* __restrict__ Pd8 = (const unsigned long long*)g_Pd;

    uint32_t h = lane >> 4;          // half-warp id: edge parity
    uint32_t q = lane & 15;          // float-pair index within row
    uint32_t nIt = E - e0; if (nIt > 32u) nIt = 32u;

    if (nIt == 32u) {
#pragma unroll 8
        for (int it = 0; it < 16; ++it) {
            uint32_t eidx = 2u * (uint32_t)it + h;
            uint32_t s = __shfl_sync(0xffffffffu, sv, eidx);
            uint32_t d = __shfl_sync(0xffffffffu, dv, eidx);
            unsigned long long a = __ldg(Ps8 + (size_t)s * 16u + q);
            unsigned long long b = __ldg(Pd8 + (size_t)d * 16u + q);
            float lo, hi;
            unpack2(add2(a, b), lo, hi);
            float* base = out + (size_t)(e0 + eidx) * C;
            if (q <= 10u) __stcs(base + 2u * q, lo);        // floats 0,2,...,20
            if (q <= 9u)  __stcs(base + 2u * q + 1u, hi);   // floats 1,3,...,19
        }
    } else {
        const float* __restrict__ Ps = g_Ps;
        const float* __restrict__ Pd = g_Pd;
        for (uint32_t it = 0; it < nIt; ++it) {
            uint32_t s = __shfl_sync(0xffffffffu, sv, it);
            uint32_t d = __shfl_sync(0xffffffffu, dv, it);
            if (lane < C) {
                float v = __ldg(&Ps[(size_t)s * PROW + lane]) +
                          __ldg(&Pd[(size_t)d * PROW + lane]);
                out[(size_t)(e0 + it) * C + lane] = v;
            }
        }
    }
}

// ---------------------------------------------------------------------------
extern "C" void kernel_launch(void* const* d_in, const int* in_sizes, int n_in,
                              void* d_out, int out_size) {
    const float*    emb   = (const float*)d_in[0];
    const uint32_t* ei    = (const uint32_t*)d_in[1];
    const float*    Wsrc  = (const float*)d_in[2];
    const float*    Wdst  = (const float*)d_in[3];
    const float*    bfuse = (const float*)d_in[4];
    const float*    Wcls  = (const float*)d_in[5];
    const float*    bcls  = (const float*)d_in[6];
    float* out = (float*)d_out;

    int N = in_sizes[0] / D;          // 50000
    int E = in_sizes[1] / 2;          // 1600000

    int tot1 = 2 * D * C + C;
    int cblocks = (tot1 + 255) / 256 + 1;   // +1 block for dtype detection
    combine_kernel<<<cblocks, 256>>>(Wsrc, Wdst, Wcls, bfuse, bcls, ei);

    int nodesPerBlock = 8 * NPT;      // 8 warps x NPT nodes
    nodeproj_kernel<<<(N + nodesPerBlock - 1) / nodesPerBlock, 256>>>(emb, N);

    uint32_t warps  = ((uint32_t)E + 31u) / 32u;
    uint32_t blocks = (warps + 7u) / 8u;
    edge_kernel<<<blocks, 256>>>(ei, out, (uint32_t)E);
}